// round 6
// baseline (speedup 1.0000x reference)
#include <cuda_runtime.h>
#include <cuda_bf16.h>

#define NP   400000
#define CH   32
#define KK   27
#define TPB  256
#define TILE 256
#define NT   ((NP + TILE - 1) / TILE)   // 1563
#define NSTG 3

// ---- device scratch (allocation-free rule) ----
__device__ float g_buf1[(size_t)NP*CH];
__device__ float g_buf2[(size_t)NP*CH];
__device__ float g_stats[128];                 // [0:64) conv1 sum/sumsq, [64:128) conv2
__device__ unsigned short g_wt[2][KK*2048];    // per-k 4KB: [Wh 2KB | Wl 2KB], swizzled
__device__ unsigned g_pk[(size_t)NP*32];       // packed rows: 128B = [hi 16w | lo 16w]
__device__ int g_fidx[(size_t)KK*NP];          // k-major folded idx (mask applied)
__device__ __align__(128) unsigned char g_zero[128];

// ---- conv smem layout (bytes) ----
#define SM_A   0                        // NSTG * TPB * 128 = 98304
#define SM_WR  (NSTG*TPB*128)           // 3 * 4096 = 12288
#define SM_ST  (SM_WR + NSTG*4096)      // 110592
#define SM_TOT (SM_ST + 256)            // 110848  -> 2 CTAs/SM

// ============ helpers ============
__device__ __forceinline__ unsigned smem_u32(const void* p){
    unsigned a; asm("{ .reg .u64 t; cvta.to.shared.u64 t, %1; cvt.u32.u64 %0, t; }"
                    : "=r"(a) : "l"(p));
    return a;
}
__device__ __forceinline__ void cpa16(unsigned dst, const void* src){
    asm volatile("cp.async.cg.shared.global [%0], [%1], 16;" :: "r"(dst), "l"(src));
}
__device__ __forceinline__ uint4 lds128(unsigned addr){
    uint4 r;
    asm volatile("ld.shared.v4.u32 {%0,%1,%2,%3}, [%4];"
        : "=r"(r.x),"=r"(r.y),"=r"(r.z),"=r"(r.w) : "r"(addr));
    return r;
}
__device__ __forceinline__ void ldmx4t(unsigned* r, unsigned addr){
    asm volatile("ldmatrix.sync.aligned.m8n8.x4.trans.shared.b16 {%0,%1,%2,%3}, [%4];"
        : "=r"(r[0]),"=r"(r[1]),"=r"(r[2]),"=r"(r[3]) : "r"(addr));
}
__device__ __forceinline__ void mma16816(float* d, const unsigned* a, const unsigned* b){
    asm volatile("mma.sync.aligned.m16n8k16.row.col.f32.bf16.bf16.f32 "
        "{%0,%1,%2,%3}, {%4,%5,%6,%7}, {%8,%9}, {%0,%1,%2,%3};"
        : "+f"(d[0]),"+f"(d[1]),"+f"(d[2]),"+f"(d[3])
        : "r"(a[0]),"r"(a[1]),"r"(a[2]),"r"(a[3]), "r"(b[0]),"r"(b[1]));
}
__device__ __forceinline__ unsigned pack_bf16(float x, float y){
    return (unsigned)__bfloat16_as_ushort(__float2bfloat16(x)) |
           ((unsigned)__bfloat16_as_ushort(__float2bfloat16(y)) << 16);
}

// ============ W prep: fp32 -> swizzled bf16 hi/lo tiles (B operand) ============
__global__ void prep_w(const float* __restrict__ W1, const float* __restrict__ W2){
    int idx = blockIdx.x*blockDim.x + threadIdx.x;
    if (idx >= 2*KK*CH*CH) return;
    int w   = idx / (KK*CH*CH);
    int rem = idx % (KK*CH*CH);
    int k = rem / (CH*CH);
    int i = (rem / CH) % CH;   // input channel  (GEMM K)  -> row
    int c = rem % CH;          // output channel (GEMM N)  -> col
    float v = (w ? W2 : W1)[(k*CH + i)*CH + c];
    __nv_bfloat16 h = __float2bfloat16(v);
    __nv_bfloat16 l = __float2bfloat16(v - __bfloat162float(h));
    unsigned off = i*64 + ((((unsigned)(c>>3)) ^ ((i>>1)&3)) << 4) + (c&7)*2;
    unsigned short* dst = g_wt[w] + k*2048;
    dst[off>>1]          = __bfloat16_as_ushort(h);
    dst[(off>>1) + 1024] = __bfloat16_as_ushort(l);
}

__global__ void zero_stats(){
    if (threadIdx.x < 128) g_stats[threadIdx.x] = 0.f;
    if (threadIdx.x < 32) ((unsigned*)g_zero)[threadIdx.x] = 0u;
}

// ============ idx transpose: (n,k) row-major + mask -> k-major folded ============
__global__ void prep_fidx(const int* __restrict__ nbr, const int* __restrict__ mask,
                          int* __restrict__ fidx)
{
    __shared__ int tmp[KK][TILE + 1];
    long long gbase = (long long)blockIdx.x * TILE * KK;
    for (int j = threadIdx.x; j < TILE*KK; j += blockDim.x){
        long long g = gbase + j;
        int v = -1;
        if (g < (long long)NP*KK && mask[g]) v = nbr[g];
        int nl = j / KK, k = j - nl*KK;
        tmp[k][nl] = v;
    }
    __syncthreads();
    int n = blockIdx.x*TILE + threadIdx.x;
    if (n < NP){
        #pragma unroll 1
        for (int k = 0; k < KK; k++) fidx[(size_t)k*NP + n] = tmp[k][threadIdx.x];
    }
}

// ============ pack input: fp32 row -> [hi 16w | lo 16w], permuted word order ============
__global__ void pack_input(const float* __restrict__ src, unsigned* __restrict__ dst,
                           int bn, const float* __restrict__ gam, const float* __restrict__ bet)
{
    long long t = (long long)blockIdx.x*blockDim.x + threadIdx.x;
    if (t >= (long long)NP*16) return;
    int q   = (int)(t & 15);
    long long row = t >> 4;
    int p = (q >> 2) + 4*(q & 3);
    int c = 2*p;
    float2 v = *(const float2*)(src + row*CH + c);
    float x = v.x, y = v.y;
    if (bn){
        float m0 = g_stats[c]   * (1.f/NP), m1 = g_stats[c+1]   * (1.f/NP);
        float q0 = g_stats[32+c]* (1.f/NP), q1 = g_stats[32+c+1]* (1.f/NP);
        float s0 = rsqrtf(q0 - m0*m0 + 1e-5f) * gam[c];
        float s1 = rsqrtf(q1 - m1*m1 + 1e-5f) * gam[c+1];
        x = fmaxf(x*s0 + (bet[c]   - m0*s0), 0.f);
        y = fmaxf(y*s1 + (bet[c+1] - m1*s1), 0.f);
    }
    float hx = __bfloat162float(__float2bfloat16(x));
    float hy = __bfloat162float(__float2bfloat16(y));
    unsigned* o = dst + row*32;
    o[q]      = pack_bf16(x, y);
    o[16 + q] = pack_bf16(x - hx, y - hy);
}

// ============ conv: cp.async 3-stage pipeline, self-read A staging, streamed W ============
__global__ void __launch_bounds__(TPB,2) conv_mma(
    const unsigned char* __restrict__ pk, const unsigned char* __restrict__ wq,
    const int* __restrict__ fidx, const unsigned char* __restrict__ zrow,
    float* __restrict__ out, int stats_off)
{
    extern __shared__ char smem[];
    const unsigned sb = smem_u32(smem);
    const int tid = threadIdx.x, w = tid >> 5, lane = tid & 31;
    const int gq = lane & 3, r_lo = lane >> 2, l7 = lane & 7;
    const int RB = w * 32;
    const int rbase = blockIdx.x*TILE + RB + r_lo;

    if (tid < 64) ((float*)(smem + SM_ST))[tid] = 0.f;

    // ---- prologue: stages 0 and 1 ----
    int irn[4];
    #pragma unroll
    for (int s = 0; s < 2; s++){
        #pragma unroll
        for (int m = 0; m < 4; m++){
            int n = rbase + m*8;
            irn[m] = (n < NP) ? fidx[(size_t)s*NP + n] : -1;
        }
        unsigned ab = sb + SM_A + s*(TPB*128) + tid*128;
        #pragma unroll
        for (int m = 0; m < 4; m++){
            const unsigned char* rp = (irn[m] >= 0) ? (pk + (size_t)irn[m]*128) : zrow;
            cpa16(ab + ((unsigned)((m     ^ l7)) << 4), rp + gq*16);
            cpa16(ab + ((unsigned)(((4+m) ^ l7)) << 4), rp + 64 + gq*16);
        }
        cpa16(sb + SM_WR + s*4096 + tid*16, wq + s*4096 + tid*16);
        asm volatile("cp.async.commit_group;" ::: "memory");
    }
    #pragma unroll
    for (int m = 0; m < 4; m++){
        int n = rbase + m*8;
        irn[m] = (n < NP) ? fidx[(size_t)2*NP + n] : -1;
    }

    float acc[2][4][4];
    #pragma unroll
    for (int a = 0; a < 2; a++)
        #pragma unroll
        for (int b = 0; b < 4; b++)
            #pragma unroll
            for (int c = 0; c < 4; c++) acc[a][b][c] = 0.f;

    int s = 0;
    #pragma unroll 1
    for (int k = 0; k < KK; k++){
        asm volatile("cp.async.wait_group 1;" ::: "memory");
        __syncthreads();

        // ---- A fragments: 8 conflict-free LDS.128 from own 128B block ----
        unsigned ab = sb + SM_A + s*(TPB*128) + tid*128;
        uint4 vh[4], vl[4];
        #pragma unroll
        for (int m = 0; m < 4; m++){
            vh[m] = lds128(ab + ((unsigned)((m     ^ l7)) << 4));
            vl[m] = lds128(ab + ((unsigned)(((4+m) ^ l7)) << 4));
        }
        // ---- B fragments from W ring slot ----
        unsigned wk = sb + SM_WR + s*4096;
        unsigned bh[4][4], bl[4][4];
        #pragma unroll
        for (int nq = 0; nq < 4; nq++){
            unsigned sw = ((((unsigned)nq) ^ ((lane>>1)&3)) << 4);
            ldmx4t(bh[nq], wk +        lane*64 + sw);
            ldmx4t(bl[nq], wk + 2048 + lane*64 + sw);
        }
        __syncthreads();

        // ---- issue stage k+2 into slot (s+2)%3 (never concurrently read) ----
        if (k + 2 < KK){
            int s2 = s + 2; if (s2 >= NSTG) s2 -= NSTG;
            unsigned ab2 = sb + SM_A + s2*(TPB*128) + tid*128;
            #pragma unroll
            for (int m = 0; m < 4; m++){
                const unsigned char* rp = (irn[m] >= 0) ? (pk + (size_t)irn[m]*128) : zrow;
                cpa16(ab2 + ((unsigned)((m     ^ l7)) << 4), rp + gq*16);
                cpa16(ab2 + ((unsigned)(((4+m) ^ l7)) << 4), rp + 64 + gq*16);
            }
            cpa16(sb + SM_WR + s2*4096 + tid*16, wq + (size_t)(k+2)*4096 + tid*16);
        }
        asm volatile("cp.async.commit_group;" ::: "memory");

        // ---- preload idx for k+3 ----
        if (k + 3 < KK){
            #pragma unroll
            for (int m = 0; m < 4; m++){
                int n = rbase + m*8;
                irn[m] = (n < NP) ? fidx[(size_t)(k+3)*NP + n] : -1;
            }
        }

        // ---- 48 mma: Ah*Wh + Al*Wh + Ah*Wl ----
        #pragma unroll
        for (int nq = 0; nq < 4; nq++){
            #pragma unroll
            for (int rb = 0; rb < 2; rb++){
                unsigned ah0[4], ah1[4], al0[4], al1[4];
                const unsigned* r0h = (const unsigned*)&vh[2*rb];
                const unsigned* r1h = (const unsigned*)&vh[2*rb+1];
                const unsigned* r0l = (const unsigned*)&vl[2*rb];
                const unsigned* r1l = (const unsigned*)&vl[2*rb+1];
                ah0[0]=r0h[0]; ah0[1]=r1h[0]; ah0[2]=r0h[1]; ah0[3]=r1h[1];
                ah1[0]=r0h[2]; ah1[1]=r1h[2]; ah1[2]=r0h[3]; ah1[3]=r1h[3];
                al0[0]=r0l[0]; al0[1]=r1l[0]; al0[2]=r0l[1]; al0[3]=r1l[1];
                al1[0]=r0l[2]; al1[1]=r1l[2]; al1[2]=r0l[3]; al1[3]=r1l[3];
                mma16816(acc[rb][nq], ah0, bh[nq] + 0);
                mma16816(acc[rb][nq], ah1, bh[nq] + 2);
                mma16816(acc[rb][nq], al0, bh[nq] + 0);
                mma16816(acc[rb][nq], al1, bh[nq] + 2);
                mma16816(acc[rb][nq], ah0, bl[nq] + 0);
                mma16816(acc[rb][nq], ah1, bl[nq] + 2);
            }
        }
        if (++s == NSTG) s = 0;
    }
    asm volatile("cp.async.wait_group 0;" ::: "memory");

    // ---- epilogue: store raw conv output + fused BN stats ----
    float sR[8], qR[8];
    #pragma unroll
    for (int i = 0; i < 8; i++){ sR[i] = 0.f; qR[i] = 0.f; }

    const int r0 = rbase;          // blockIdx*TILE + RB + r_lo
    const int C0 = gq * 2;
    #pragma unroll
    for (int rb = 0; rb < 2; rb++){
        #pragma unroll
        for (int nq = 0; nq < 4; nq++){
            float a0 = acc[rb][nq][0], a1 = acc[rb][nq][1];
            float a2 = acc[rb][nq][2], a3 = acc[rb][nq][3];
            int m0 = r0 + rb*16, m1 = m0 + 8;
            int c  = nq*8 + C0;
            if (m0 < NP) *(float2*)(out + (size_t)m0*CH + c) = make_float2(a0, a1);
            if (m1 < NP) *(float2*)(out + (size_t)m1*CH + c) = make_float2(a2, a3);
            sR[nq*2+0] += a0 + a2;  qR[nq*2+0] += a0*a0 + a2*a2;
            sR[nq*2+1] += a1 + a3;  qR[nq*2+1] += a1*a1 + a3*a3;
        }
    }
    #pragma unroll
    for (int i = 0; i < 8; i++){
        #pragma unroll
        for (int off = 4; off < 32; off <<= 1){
            sR[i] += __shfl_xor_sync(0xffffffffu, sR[i], off);
            qR[i] += __shfl_xor_sync(0xffffffffu, qR[i], off);
        }
    }
    if (lane < 4){
        float* st = (float*)(smem + SM_ST);
        #pragma unroll
        for (int nq = 0; nq < 4; nq++){
            atomicAdd(&st[     nq*8 + lane*2    ], sR[nq*2+0]);
            atomicAdd(&st[     nq*8 + lane*2 + 1], sR[nq*2+1]);
            atomicAdd(&st[32 + nq*8 + lane*2    ], qR[nq*2+0]);
            atomicAdd(&st[32 + nq*8 + lane*2 + 1], qR[nq*2+1]);
        }
    }
    __syncthreads();
    if (tid < 64) atomicAdd(&g_stats[stats_off + tid], ((float*)(smem + SM_ST))[tid]);
}

// ---- final BN + residual + ReLU ----
__global__ void bnrelu_kernel(const float4* __restrict__ x, int stats_off,
    const float* __restrict__ gamma, const float* __restrict__ beta,
    const float4* __restrict__ res, float4* __restrict__ out)
{
    long long i = (long long)blockIdx.x*blockDim.x + threadIdx.x;
    if (i >= (long long)NP*CH/4) return;
    int c0 = (int)(i & 7) * 4;
    const float invN = 1.0f / NP;
    float4 v = x[i];
    float4 r4 = res[i];
    float4 o;
#define BN_ONE(comp, c) { \
        float mean = g_stats[stats_off + c0 + c] * invN; \
        float var  = g_stats[stats_off + 32 + c0 + c] * invN - mean*mean; \
        float sc   = rsqrtf(var + 1e-5f) * gamma[c0 + c]; \
        float val  = (v.comp - mean)*sc + beta[c0 + c] + r4.comp; \
        o.comp = fmaxf(val, 0.f); }
    BN_ONE(x, 0) BN_ONE(y, 1) BN_ONE(z, 2) BN_ONE(w, 3)
#undef BN_ONE
    out[i] = o;
}

extern "C" void kernel_launch(void* const* d_in, const int* in_sizes, int n_in,
                              void* d_out, int out_size)
{
    const float* feats  = (const float*)d_in[0];
    const float* W1     = (const float*)d_in[1];
    const float* gamma1 = (const float*)d_in[2];
    const float* beta1  = (const float*)d_in[3];
    const float* W2     = (const float*)d_in[4];
    const float* gamma2 = (const float*)d_in[5];
    const float* beta2  = (const float*)d_in[6];
    const int*   nbr    = (const int*)d_in[7];
    const int*   mask   = (const int*)d_in[8];
    float* out = (float*)d_out;

    float *buf1, *buf2; unsigned short* wt; unsigned* pk; int* fidx; unsigned char* zr;
    cudaGetSymbolAddress((void**)&buf1, g_buf1);
    cudaGetSymbolAddress((void**)&buf2, g_buf2);
    cudaGetSymbolAddress((void**)&wt,   g_wt);
    cudaGetSymbolAddress((void**)&pk,   g_pk);
    cudaGetSymbolAddress((void**)&fidx, g_fidx);
    cudaGetSymbolAddress((void**)&zr,   g_zero);

    cudaFuncSetAttribute(conv_mma, cudaFuncAttributeMaxDynamicSharedMemorySize, SM_TOT);

    const long long ne4 = (long long)NP*CH/4;
    const int gridb = (int)((ne4 + 255) / 256);
    const int gridp = (int)(((long long)NP*16 + 255) / 256);

    zero_stats<<<1,128>>>();
    prep_w<<<(2*KK*CH*CH + 255)/256, 256>>>(W1, W2);
    prep_fidx<<<NT, 256>>>(nbr, mask, fidx);
    // pack feats -> pk; conv1: raw -> buf1, stats@0
    pack_input<<<gridp, 256>>>(feats, pk, 0, (const float*)0, (const float*)0);
    conv_mma<<<NT, TPB, SM_TOT>>>((const unsigned char*)pk, (const unsigned char*)wt,
                                  fidx, zr, buf1, 0);
    // h = relu(bn1(buf1)) packed -> pk; conv2: raw -> buf2, stats@64
    pack_input<<<gridp, 256>>>(buf1, pk, 1, gamma1, beta1);
    conv_mma<<<NT, TPB, SM_TOT>>>((const unsigned char*)pk,
                                  (const unsigned char*)(wt + KK*2048),
                                  fidx, zr, buf2, 64);
    // out = relu(BN2(buf2) + feats)
    bnrelu_kernel<<<gridb, 256>>>((const float4*)buf2, 64, gamma2, beta2,
                                  (const float4*)feats, (float4*)out);
}

// round 7
// speedup vs baseline: 34.0297x; 34.0297x over previous
#include <cuda_runtime.h>
#include <cuda_bf16.h>

#define NP   400000
#define CH   32
#define KK   27
#define TPB  384
#define TILE 384
#define NT   ((NP + TILE - 1) / TILE)   // 1042
#define BT   256
#define NT2  ((NP + BT - 1) / BT)

// ---- device scratch (allocation-free rule) ----
__device__ float g_buf1[(size_t)NP*CH];
__device__ float g_buf2[(size_t)NP*CH];
__device__ float g_stats[128];                   // [0:64) conv1 sum/sumsq, [64:128) conv2
__device__ unsigned short g_wt[2][KK*2048];      // per-k 4KB: [Wh 2KB | Wl 2KB], swizzled
__device__ unsigned g_pk[((size_t)NP+1)*32];     // packed rows 128B = [hi 16w | lo 16w]; row NP = zeros
__device__ int g_fidx[(size_t)KK*NP];            // k-major folded idx (mask applied; NP = inactive)

// ---- conv smem layout (bytes) ----
#define SM_W   0                        // 27*4096 = 110592
#define SM_ST  110592                   // 64 floats
#define SM_TOT (SM_ST + 256)            // 110848

// ============ helpers ============
__device__ __forceinline__ unsigned smem_u32(const void* p){
    unsigned a; asm("{ .reg .u64 t; cvta.to.shared.u64 t, %1; cvt.u32.u64 %0, t; }"
                    : "=r"(a) : "l"(p));
    return a;
}
__device__ __forceinline__ void ldmx4t(unsigned* r, unsigned addr){
    asm volatile("ldmatrix.sync.aligned.m8n8.x4.trans.shared.b16 {%0,%1,%2,%3}, [%4];"
        : "=r"(r[0]),"=r"(r[1]),"=r"(r[2]),"=r"(r[3]) : "r"(addr));
}
__device__ __forceinline__ void mma16816(float* d, const unsigned* a, const unsigned* b){
    asm volatile("mma.sync.aligned.m16n8k16.row.col.f32.bf16.bf16.f32 "
        "{%0,%1,%2,%3}, {%4,%5,%6,%7}, {%8,%9}, {%0,%1,%2,%3};"
        : "+f"(d[0]),"+f"(d[1]),"+f"(d[2]),"+f"(d[3])
        : "r"(a[0]),"r"(a[1]),"r"(a[2]),"r"(a[3]), "r"(b[0]),"r"(b[1]));
}
__device__ __forceinline__ unsigned pack_bf16(float x, float y){
    return (unsigned)__bfloat16_as_ushort(__float2bfloat16(x)) |
           ((unsigned)__bfloat16_as_ushort(__float2bfloat16(y)) << 16);
}

// ============ W prep: fp32 -> swizzled bf16 hi/lo tiles (B operand) ============
__global__ void prep_w(const float* __restrict__ W1, const float* __restrict__ W2){
    int idx = blockIdx.x*blockDim.x + threadIdx.x;
    if (idx >= 2*KK*CH*CH) return;
    int w   = idx / (KK*CH*CH);
    int rem = idx % (KK*CH*CH);
    int k = rem / (CH*CH);
    int i = (rem / CH) % CH;   // input channel  (GEMM K)  -> row
    int c = rem % CH;          // output channel (GEMM N)  -> col
    float v = (w ? W2 : W1)[(k*CH + i)*CH + c];
    __nv_bfloat16 h = __float2bfloat16(v);
    __nv_bfloat16 l = __float2bfloat16(v - __bfloat162float(h));
    unsigned off = i*64 + ((((unsigned)(c>>3)) ^ ((i>>1)&3)) << 4) + (c&7)*2;
    unsigned short* dst = g_wt[w] + k*2048;
    dst[off>>1]          = __bfloat16_as_ushort(h);
    dst[(off>>1) + 1024] = __bfloat16_as_ushort(l);
}

__global__ void zero_stats(){
    if (threadIdx.x < 128) g_stats[threadIdx.x] = 0.f;
    if (threadIdx.x < 32)  g_pk[(size_t)NP*32 + threadIdx.x] = 0u;   // zero sentinel row
}

// ============ idx transpose: (n,k) row-major + mask -> k-major folded ============
__global__ void prep_fidx(const int* __restrict__ nbr, const int* __restrict__ mask,
                          int* __restrict__ fidx)
{
    __shared__ int tmp[KK][BT + 1];
    long long gbase = (long long)blockIdx.x * BT * KK;
    for (int j = threadIdx.x; j < BT*KK; j += blockDim.x){
        long long g = gbase + j;
        int v = NP;
        if (g < (long long)NP*KK && mask[g]) v = nbr[g];
        int nl = j / KK, k = j - nl*KK;
        tmp[k][nl] = v;
    }
    __syncthreads();
    int n = blockIdx.x*BT + threadIdx.x;
    if (n < NP){
        #pragma unroll 1
        for (int k = 0; k < KK; k++) fidx[(size_t)k*NP + n] = tmp[k][threadIdx.x];
    }
}

// ============ pack input: fp32 row -> [hi 16w | lo 16w], permuted word order ============
__global__ void pack_input(const float* __restrict__ src, unsigned* __restrict__ dst,
                           int bn, const float* __restrict__ gam, const float* __restrict__ bet)
{
    long long t = (long long)blockIdx.x*blockDim.x + threadIdx.x;
    if (t >= (long long)NP*16) return;
    int q   = (int)(t & 15);
    long long row = t >> 4;
    int p = (q >> 2) + 4*(q & 3);
    int c = 2*p;
    float2 v = *(const float2*)(src + row*CH + c);
    float x = v.x, y = v.y;
    if (bn){
        float m0 = g_stats[c]   * (1.f/NP), m1 = g_stats[c+1]   * (1.f/NP);
        float q0 = g_stats[32+c]* (1.f/NP), q1 = g_stats[32+c+1]* (1.f/NP);
        float s0 = rsqrtf(q0 - m0*m0 + 1e-5f) * gam[c];
        float s1 = rsqrtf(q1 - m1*m1 + 1e-5f) * gam[c+1];
        x = fmaxf(x*s0 + (bet[c]   - m0*s0), 0.f);
        y = fmaxf(y*s1 + (bet[c+1] - m1*s1), 0.f);
    }
    float hx = __bfloat162float(__float2bfloat16(x));
    float hy = __bfloat162float(__float2bfloat16(y));
    unsigned* o = dst + row*32;
    o[q]      = pack_bf16(x, y);
    o[16 + q] = pack_bf16(x - hx, y - hy);
}

// ============ conv: depth-2 register pipeline, warp k-rotation ============
__global__ void __launch_bounds__(TPB,1) conv_mma(
    const unsigned char* __restrict__ pk, const unsigned short* __restrict__ wt,
    const int* __restrict__ fidx, float* __restrict__ out, int stats_off)
{
    extern __shared__ char smem[];
    const unsigned sb = smem_u32(smem);
    const int tid = threadIdx.x, w = tid >> 5, lane = tid & 31;
    const int gq = lane & 3, r_lo = lane >> 2;
    const int rbase = blockIdx.x*TILE + w*32 + r_lo;

    if (tid < 64) ((float*)(smem + SM_ST))[tid] = 0.f;
    // W tiles -> smem (110592B)
    {
        const uint4* s = (const uint4*)wt;
        uint4* d = (uint4*)(smem + SM_W);
        #pragma unroll 1
        for (int i = tid; i < (KK*4096)/16; i += TPB) d[i] = s[i];
    }
    __syncthreads();

    const int k0 = (w*9) >> 2;          // warp k-rotation: 0,2,4,6,9,11,...
    int nrow[4];
    #pragma unroll
    for (int m = 0; m < 4; m++){ int n = rbase + m*8; nrow[m] = (n < NP) ? n : -1; }

    uint4 vh[2][4], vl[2][4];
    int irC[4];

    // ---- prologue: issue j=0 (buf0), j=1 (buf1); preload idx for j=2 ----
    #pragma unroll
    for (int j = 0; j < 2; j++){
        int kk = k0 + j; if (kk >= KK) kk -= KK;
        #pragma unroll
        for (int m = 0; m < 4; m++){
            int ir = (nrow[m] >= 0) ? fidx[(size_t)kk*NP + nrow[m]] : NP;
            const unsigned char* rp = pk + (size_t)ir*128;
            vh[j][m] = *(const uint4*)(rp + gq*16);
            vl[j][m] = *(const uint4*)(rp + 64 + gq*16);
        }
    }
    {
        int kk = k0 + 2; if (kk >= KK) kk -= KK;
        #pragma unroll
        for (int m = 0; m < 4; m++)
            irC[m] = (nrow[m] >= 0) ? fidx[(size_t)kk*NP + nrow[m]] : NP;
    }

    float acc[2][4][4];
    #pragma unroll
    for (int a = 0; a < 2; a++)
        #pragma unroll
        for (int b = 0; b < 4; b++)
            #pragma unroll
            for (int c = 0; c < 4; c++) acc[a][b][c] = 0.f;

    #pragma unroll 2
    for (int j = 0; j < KK; j++){
        const int buf = j & 1;
        int kk = k0 + j; if (kk >= KK) kk -= KK;

        // ---- snapshot fragments from arrived buffer ----
        unsigned ah[2][2][4], al[2][2][4];
        #pragma unroll
        for (int rb = 0; rb < 2; rb++){
            const unsigned* r0h = (const unsigned*)&vh[buf][2*rb];
            const unsigned* r1h = (const unsigned*)&vh[buf][2*rb+1];
            const unsigned* r0l = (const unsigned*)&vl[buf][2*rb];
            const unsigned* r1l = (const unsigned*)&vl[buf][2*rb+1];
            ah[rb][0][0]=r0h[0]; ah[rb][0][1]=r1h[0]; ah[rb][0][2]=r0h[1]; ah[rb][0][3]=r1h[1];
            ah[rb][1][0]=r0h[2]; ah[rb][1][1]=r1h[2]; ah[rb][1][2]=r0h[3]; ah[rb][1][3]=r1h[3];
            al[rb][0][0]=r0l[0]; al[rb][0][1]=r1l[0]; al[rb][0][2]=r0l[1]; al[rb][0][3]=r1l[1];
            al[rb][1][0]=r0l[2]; al[rb][1][1]=r1l[2]; al[rb][1][2]=r0l[3]; al[rb][1][3]=r1l[3];
        }

        // ---- issue j+2 into freed buffer ----
        if (j + 2 < KK){
            #pragma unroll
            for (int m = 0; m < 4; m++){
                const unsigned char* rp = pk + (size_t)irC[m]*128;
                vh[buf][m] = *(const uint4*)(rp + gq*16);
                vl[buf][m] = *(const uint4*)(rp + 64 + gq*16);
            }
        }
        // ---- preload idx for j+3 ----
        if (j + 3 < KK){
            int k3 = k0 + j + 3; if (k3 >= KK) k3 -= KK;
            #pragma unroll
            for (int m = 0; m < 4; m++)
                irC[m] = (nrow[m] >= 0) ? fidx[(size_t)k3*NP + nrow[m]] : NP;
        }

        // ---- B per-nq + 48 mma ----
        const unsigned wk = sb + SM_W + kk*4096;
        #pragma unroll
        for (int nq = 0; nq < 4; nq++){
            unsigned bh[4], bl4[4];
            unsigned sw = ((((unsigned)nq) ^ ((lane>>1)&3)) << 4);
            ldmx4t(bh,  wk +        lane*64 + sw);
            ldmx4t(bl4, wk + 2048 + lane*64 + sw);
            #pragma unroll
            for (int rb = 0; rb < 2; rb++){
                mma16816(acc[rb][nq], ah[rb][0], bh + 0);
                mma16816(acc[rb][nq], ah[rb][1], bh + 2);
                mma16816(acc[rb][nq], al[rb][0], bh + 0);
                mma16816(acc[rb][nq], al[rb][1], bh + 2);
                mma16816(acc[rb][nq], ah[rb][0], bl4 + 0);
                mma16816(acc[rb][nq], ah[rb][1], bl4 + 2);
            }
        }
    }

    // ---- epilogue: store raw conv output + fused BN stats ----
    float sR[8], qR[8];
    #pragma unroll
    for (int i = 0; i < 8; i++){ sR[i] = 0.f; qR[i] = 0.f; }

    const int C0 = gq * 2;
    #pragma unroll
    for (int rb = 0; rb < 2; rb++){
        #pragma unroll
        for (int nq = 0; nq < 4; nq++){
            float a0 = acc[rb][nq][0], a1 = acc[rb][nq][1];
            float a2 = acc[rb][nq][2], a3 = acc[rb][nq][3];
            int m0 = rbase + rb*16, m1 = m0 + 8;
            int c  = nq*8 + C0;
            if (m0 < NP) *(float2*)(out + (size_t)m0*CH + c) = make_float2(a0, a1);
            if (m1 < NP) *(float2*)(out + (size_t)m1*CH + c) = make_float2(a2, a3);
            sR[nq*2+0] += a0 + a2;  qR[nq*2+0] += a0*a0 + a2*a2;
            sR[nq*2+1] += a1 + a3;  qR[nq*2+1] += a1*a1 + a3*a3;
        }
    }
    #pragma unroll
    for (int i = 0; i < 8; i++){
        #pragma unroll
        for (int off = 4; off < 32; off <<= 1){
            sR[i] += __shfl_xor_sync(0xffffffffu, sR[i], off);
            qR[i] += __shfl_xor_sync(0xffffffffu, qR[i], off);
        }
    }
    if (lane < 4){
        float* st = (float*)(smem + SM_ST);
        #pragma unroll
        for (int nq = 0; nq < 4; nq++){
            atomicAdd(&st[     nq*8 + lane*2    ], sR[nq*2+0]);
            atomicAdd(&st[     nq*8 + lane*2 + 1], sR[nq*2+1]);
            atomicAdd(&st[32 + nq*8 + lane*2    ], qR[nq*2+0]);
            atomicAdd(&st[32 + nq*8 + lane*2 + 1], qR[nq*2+1]);
        }
    }
    __syncthreads();
    if (tid < 64) atomicAdd(&g_stats[stats_off + tid], ((float*)(smem + SM_ST))[tid]);
}

// ---- final BN + residual + ReLU ----
__global__ void bnrelu_kernel(const float4* __restrict__ x, int stats_off,
    const float* __restrict__ gamma, const float* __restrict__ beta,
    const float4* __restrict__ res, float4* __restrict__ out)
{
    long long i = (long long)blockIdx.x*blockDim.x + threadIdx.x;
    if (i >= (long long)NP*CH/4) return;
    int c0 = (int)(i & 7) * 4;
    const float invN = 1.0f / NP;
    float4 v = x[i];
    float4 r4 = res[i];
    float4 o;
#define BN_ONE(comp, c) { \
        float mean = g_stats[stats_off + c0 + c] * invN; \
        float var  = g_stats[stats_off + 32 + c0 + c] * invN - mean*mean; \
        float sc   = rsqrtf(var + 1e-5f) * gamma[c0 + c]; \
        float val  = (v.comp - mean)*sc + beta[c0 + c] + r4.comp; \
        o.comp = fmaxf(val, 0.f); }
    BN_ONE(x, 0) BN_ONE(y, 1) BN_ONE(z, 2) BN_ONE(w, 3)
#undef BN_ONE
    out[i] = o;
}

extern "C" void kernel_launch(void* const* d_in, const int* in_sizes, int n_in,
                              void* d_out, int out_size)
{
    const float* feats  = (const float*)d_in[0];
    const float* W1     = (const float*)d_in[1];
    const float* gamma1 = (const float*)d_in[2];
    const float* beta1  = (const float*)d_in[3];
    const float* W2     = (const float*)d_in[4];
    const float* gamma2 = (const float*)d_in[5];
    const float* beta2  = (const float*)d_in[6];
    const int*   nbr    = (const int*)d_in[7];
    const int*   mask   = (const int*)d_in[8];
    float* out = (float*)d_out;

    float *buf1, *buf2; unsigned short* wt; unsigned* pk; int* fidx;
    cudaGetSymbolAddress((void**)&buf1, g_buf1);
    cudaGetSymbolAddress((void**)&buf2, g_buf2);
    cudaGetSymbolAddress((void**)&wt,   g_wt);
    cudaGetSymbolAddress((void**)&pk,   g_pk);
    cudaGetSymbolAddress((void**)&fidx, g_fidx);

    cudaFuncSetAttribute(conv_mma, cudaFuncAttributeMaxDynamicSharedMemorySize, SM_TOT);

    const long long ne4 = (long long)NP*CH/4;
    const int gridb = (int)((ne4 + 255) / 256);
    const int gridp = (int)(((long long)NP*16 + 255) / 256);

    zero_stats<<<1,128>>>();
    prep_w<<<(2*KK*CH*CH + 255)/256, 256>>>(W1, W2);
    prep_fidx<<<NT2, 256>>>(nbr, mask, fidx);
    // pack feats -> pk; conv1: raw -> buf1, stats@0
    pack_input<<<gridp, 256>>>(feats, pk, 0, (const float*)0, (const float*)0);
    conv_mma<<<NT, TPB, SM_TOT>>>((const unsigned char*)pk, wt, fidx, buf1, 0);
    // h = relu(bn1(buf1)) packed -> pk; conv2: raw -> buf2, stats@64
    pack_input<<<gridp, 256>>>(buf1, pk, 1, gamma1, beta1);
    conv_mma<<<NT, TPB, SM_TOT>>>((const unsigned char*)pk, wt + KK*2048, fidx, buf2, 64);
    // out = relu(BN2(buf2) + feats)
    bnrelu_kernel<<<gridb, 256>>>((const float4*)buf2, 64, gamma2, beta2,
                                  (const float4*)feats, (float4*)out);
}

// round 8
// speedup vs baseline: 49.0604x; 1.4417x over previous
#include <cuda_runtime.h>
#include <cuda_fp16.h>

#define NP   400000
#define CH   32
#define KK   27
#define TPB  256
#define TILE 256
#define NT   ((NP + TILE - 1) / TILE)   // 1563
#define BT   256
#define NT2  ((NP + BT - 1) / BT)

// ---- device scratch (allocation-free rule) ----
__device__ float g_buf1[(size_t)NP*CH];
__device__ float g_buf2[(size_t)NP*CH];
__device__ float g_stats[128];                   // [0:64) conv1 sum/sumsq, [64:128) conv2
__device__ unsigned short g_wt[2][KK*2048];      // per-k 4KB: [Wh 2KB | Wl 2KB] fp16, swizzled
__device__ unsigned g_pk[((size_t)NP+1)*16];     // packed fp16 rows 64B; row NP = zeros
__device__ int g_fidx[(size_t)KK*NP];            // k-major folded idx (mask applied; NP = inactive)

// ---- conv smem layout (bytes) ----
#define SM_W   0                        // 27*4096 = 110592
#define SM_ST  110592                   // 64 floats
#define SM_TOT (SM_ST + 256)            // 110848 -> 2 CTAs/SM

// ============ helpers ============
__device__ __forceinline__ unsigned smem_u32(const void* p){
    unsigned a; asm("{ .reg .u64 t; cvta.to.shared.u64 t, %1; cvt.u32.u64 %0, t; }"
                    : "=r"(a) : "l"(p));
    return a;
}
__device__ __forceinline__ void ldmx4t(unsigned* r, unsigned addr){
    asm volatile("ldmatrix.sync.aligned.m8n8.x4.trans.shared.b16 {%0,%1,%2,%3}, [%4];"
        : "=r"(r[0]),"=r"(r[1]),"=r"(r[2]),"=r"(r[3]) : "r"(addr));
}
__device__ __forceinline__ void mma16816h(float* d, const unsigned* a, const unsigned* b){
    asm volatile("mma.sync.aligned.m16n8k16.row.col.f32.f16.f16.f32 "
        "{%0,%1,%2,%3}, {%4,%5,%6,%7}, {%8,%9}, {%0,%1,%2,%3};"
        : "+f"(d[0]),"+f"(d[1]),"+f"(d[2]),"+f"(d[3])
        : "r"(a[0]),"r"(a[1]),"r"(a[2]),"r"(a[3]), "r"(b[0]),"r"(b[1]));
}
__device__ __forceinline__ unsigned pack_f16(float x, float y){
    __half2 h = __floats2half2_rn(x, y);
    return *(unsigned*)&h;
}

// ============ W prep: fp32 -> swizzled fp16 hi/lo tiles (B operand) ============
__global__ void prep_w(const float* __restrict__ W1, const float* __restrict__ W2){
    int idx = blockIdx.x*blockDim.x + threadIdx.x;
    if (idx >= 2*KK*CH*CH) return;
    int w   = idx / (KK*CH*CH);
    int rem = idx % (KK*CH*CH);
    int k = rem / (CH*CH);
    int i = (rem / CH) % CH;   // input channel  (GEMM K)  -> row
    int c = rem % CH;          // output channel (GEMM N)  -> col
    float v = (w ? W2 : W1)[(k*CH + i)*CH + c];
    __half h = __float2half_rn(v);
    __half l = __float2half_rn(v - __half2float(h));
    unsigned off = i*64 + ((((unsigned)(c>>3)) ^ ((i>>1)&3)) << 4) + (c&7)*2;
    unsigned short* dst = g_wt[w] + k*2048;
    dst[off>>1]          = __half_as_ushort(h);
    dst[(off>>1) + 1024] = __half_as_ushort(l);
}

__global__ void zero_stats(){
    if (threadIdx.x < 128) g_stats[threadIdx.x] = 0.f;
    if (threadIdx.x < 16)  g_pk[(size_t)NP*16 + threadIdx.x] = 0u;   // zero sentinel row
}

// ============ idx transpose: (n,k) row-major + mask -> k-major folded ============
__global__ void prep_fidx(const int* __restrict__ nbr, const int* __restrict__ mask,
                          int* __restrict__ fidx)
{
    __shared__ int tmp[KK][BT + 1];
    long long gbase = (long long)blockIdx.x * BT * KK;
    for (int j = threadIdx.x; j < BT*KK; j += blockDim.x){
        long long g = gbase + j;
        int v = NP;
        if (g < (long long)NP*KK && mask[g]) v = nbr[g];
        int nl = j / KK, k = j - nl*KK;
        tmp[k][nl] = v;
    }
    __syncthreads();
    int n = blockIdx.x*BT + threadIdx.x;
    if (n < NP){
        #pragma unroll 1
        for (int k = 0; k < KK; k++) fidx[(size_t)k*NP + n] = tmp[k][threadIdx.x];
    }
}

// ============ pack input: fp32 row -> 16 fp16-pair words, permuted word order ============
// word q (0..15) holds channel pair p = (q>>2) + 4*(q&3)
__global__ void pack_input(const float* __restrict__ src, unsigned* __restrict__ dst,
                           int bn, const float* __restrict__ gam, const float* __restrict__ bet)
{
    long long t = (long long)blockIdx.x*blockDim.x + threadIdx.x;
    if (t >= (long long)NP*16) return;
    int q   = (int)(t & 15);
    long long row = t >> 4;
    int p = (q >> 2) + 4*(q & 3);
    int c = 2*p;
    float2 v = *(const float2*)(src + row*CH + c);
    float x = v.x, y = v.y;
    if (bn){
        float m0 = g_stats[c]   * (1.f/NP), m1 = g_stats[c+1]   * (1.f/NP);
        float q0 = g_stats[32+c]* (1.f/NP), q1 = g_stats[32+c+1]* (1.f/NP);
        float s0 = rsqrtf(q0 - m0*m0 + 1e-5f) * gam[c];
        float s1 = rsqrtf(q1 - m1*m1 + 1e-5f) * gam[c+1];
        x = fmaxf(x*s0 + (bet[c]   - m0*s0), 0.f);
        y = fmaxf(y*s1 + (bet[c+1] - m1*s1), 0.f);
    }
    dst[row*16 + q] = pack_f16(x, y);
}

// ============ conv: fp16 A single-term, fp16 W two-term, depth-2 pipeline ============
__global__ void __launch_bounds__(TPB,2) conv_mma(
    const unsigned char* __restrict__ pk, const unsigned short* __restrict__ wt,
    const int* __restrict__ fidx, float* __restrict__ out, int stats_off)
{
    extern __shared__ char smem[];
    const unsigned sb = smem_u32(smem);
    const int tid = threadIdx.x, w = tid >> 5, lane = tid & 31;
    const int gq = lane & 3, r_lo = lane >> 2;
    const int rbase = blockIdx.x*TILE + w*32 + r_lo;

    if (tid < 64) ((float*)(smem + SM_ST))[tid] = 0.f;
    // W tiles -> smem (110592B)
    {
        const uint4* s = (const uint4*)wt;
        uint4* d = (uint4*)(smem + SM_W);
        #pragma unroll 1
        for (int i = tid; i < (KK*4096)/16; i += TPB) d[i] = s[i];
    }
    __syncthreads();

    const int k0 = (w*27) >> 3;          // warp k-rotation (8 warps)
    int nrow[4];
    #pragma unroll
    for (int m = 0; m < 4; m++){ int n = rbase + m*8; nrow[m] = (n < NP) ? n : -1; }

    uint4 vh[2][4];
    int irC[4];

    // ---- prologue: issue j=0,1; preload idx for j=2 ----
    #pragma unroll
    for (int j = 0; j < 2; j++){
        int kk = k0 + j; if (kk >= KK) kk -= KK;
        #pragma unroll
        for (int m = 0; m < 4; m++){
            int ir = (nrow[m] >= 0) ? fidx[(size_t)kk*NP + nrow[m]] : NP;
            vh[j][m] = *(const uint4*)(pk + (size_t)ir*64 + gq*16);
        }
    }
    {
        int kk = k0 + 2; if (kk >= KK) kk -= KK;
        #pragma unroll
        for (int m = 0; m < 4; m++)
            irC[m] = (nrow[m] >= 0) ? fidx[(size_t)kk*NP + nrow[m]] : NP;
    }

    float acc[2][4][4];
    #pragma unroll
    for (int a = 0; a < 2; a++)
        #pragma unroll
        for (int b = 0; b < 4; b++)
            #pragma unroll
            for (int c = 0; c < 4; c++) acc[a][b][c] = 0.f;

    #pragma unroll 2
    for (int j = 0; j < KK; j++){
        const int buf = j & 1;
        int kk = k0 + j; if (kk >= KK) kk -= KK;

        // ---- snapshot fragments from arrived buffer ----
        unsigned ah[2][2][4];
        #pragma unroll
        for (int rb = 0; rb < 2; rb++){
            const unsigned* r0 = (const unsigned*)&vh[buf][2*rb];
            const unsigned* r1 = (const unsigned*)&vh[buf][2*rb+1];
            ah[rb][0][0]=r0[0]; ah[rb][0][1]=r1[0]; ah[rb][0][2]=r0[1]; ah[rb][0][3]=r1[1];
            ah[rb][1][0]=r0[2]; ah[rb][1][1]=r1[2]; ah[rb][1][2]=r0[3]; ah[rb][1][3]=r1[3];
        }

        // ---- issue j+2 into freed buffer ----
        if (j + 2 < KK){
            #pragma unroll
            for (int m = 0; m < 4; m++)
                vh[buf][m] = *(const uint4*)(pk + (size_t)irC[m]*64 + gq*16);
        }
        // ---- preload idx for j+3 ----
        if (j + 3 < KK){
            int k3 = k0 + j + 3; if (k3 >= KK) k3 -= KK;
            #pragma unroll
            for (int m = 0; m < 4; m++)
                irC[m] = (nrow[m] >= 0) ? fidx[(size_t)k3*NP + nrow[m]] : NP;
        }

        // ---- B per-nq + 32 mma: Ah*Wh + Ah*Wl ----
        const unsigned wk = sb + SM_W + kk*4096;
        #pragma unroll
        for (int nq = 0; nq < 4; nq++){
            unsigned bh[4], bl4[4];
            unsigned sw = ((((unsigned)nq) ^ ((lane>>1)&3)) << 4);
            ldmx4t(bh,  wk +        lane*64 + sw);
            ldmx4t(bl4, wk + 2048 + lane*64 + sw);
            #pragma unroll
            for (int rb = 0; rb < 2; rb++){
                mma16816h(acc[rb][nq], ah[rb][0], bh + 0);
                mma16816h(acc[rb][nq], ah[rb][1], bh + 2);
                mma16816h(acc[rb][nq], ah[rb][0], bl4 + 0);
                mma16816h(acc[rb][nq], ah[rb][1], bl4 + 2);
            }
        }
    }

    // ---- epilogue: store raw conv output + fused BN stats ----
    float sR[8], qR[8];
    #pragma unroll
    for (int i = 0; i < 8; i++){ sR[i] = 0.f; qR[i] = 0.f; }

    const int C0 = gq * 2;
    #pragma unroll
    for (int rb = 0; rb < 2; rb++){
        #pragma unroll
        for (int nq = 0; nq < 4; nq++){
            float a0 = acc[rb][nq][0], a1 = acc[rb][nq][1];
            float a2 = acc[rb][nq][2], a3 = acc[rb][nq][3];
            int m0 = rbase + rb*16, m1 = m0 + 8;
            int c  = nq*8 + C0;
            if (m0 < NP) *(float2*)(out + (size_t)m0*CH + c) = make_float2(a0, a1);
            if (m1 < NP) *(float2*)(out + (size_t)m1*CH + c) = make_float2(a2, a3);
            sR[nq*2+0] += a0 + a2;  qR[nq*2+0] += a0*a0 + a2*a2;
            sR[nq*2+1] += a1 + a3;  qR[nq*2+1] += a1*a1 + a3*a3;
        }
    }
    #pragma unroll
    for (int i = 0; i < 8; i++){
        #pragma unroll
        for (int off = 4; off < 32; off <<= 1){
            sR[i] += __shfl_xor_sync(0xffffffffu, sR[i], off);
            qR[i] += __shfl_xor_sync(0xffffffffu, qR[i], off);
        }
    }
    if (lane < 4){
        float* st = (float*)(smem + SM_ST);
        #pragma unroll
        for (int nq = 0; nq < 4; nq++){
            atomicAdd(&st[     nq*8 + lane*2    ], sR[nq*2+0]);
            atomicAdd(&st[     nq*8 + lane*2 + 1], sR[nq*2+1]);
            atomicAdd(&st[32 + nq*8 + lane*2    ], qR[nq*2+0]);
            atomicAdd(&st[32 + nq*8 + lane*2 + 1], qR[nq*2+1]);
        }
    }
    __syncthreads();
    if (tid < 64) atomicAdd(&g_stats[stats_off + tid], ((float*)(smem + SM_ST))[tid]);
}

// ---- final BN + residual + ReLU ----
__global__ void bnrelu_kernel(const float4* __restrict__ x, int stats_off,
    const float* __restrict__ gamma, const float* __restrict__ beta,
    const float4* __restrict__ res, float4* __restrict__ out)
{
    long long i = (long long)blockIdx.x*blockDim.x + threadIdx.x;
    if (i >= (long long)NP*CH/4) return;
    int c0 = (int)(i & 7) * 4;
    const float invN = 1.0f / NP;
    float4 v = x[i];
    float4 r4 = res[i];
    float4 o;
#define BN_ONE(comp, c) { \
        float mean = g_stats[stats_off + c0 + c] * invN; \
        float var  = g_stats[stats_off + 32 + c0 + c] * invN - mean*mean; \
        float sc   = rsqrtf(var + 1e-5f) * gamma[c0 + c]; \
        float val  = (v.comp - mean)*sc + beta[c0 + c] + r4.comp; \
        o.comp = fmaxf(val, 0.f); }
    BN_ONE(x, 0) BN_ONE(y, 1) BN_ONE(z, 2) BN_ONE(w, 3)
#undef BN_ONE
    out[i] = o;
}

extern "C" void kernel_launch(void* const* d_in, const int* in_sizes, int n_in,
                              void* d_out, int out_size)
{
    const float* feats  = (const float*)d_in[0];
    const float* W1     = (const float*)d_in[1];
    const float* gamma1 = (const float*)d_in[2];
    const float* beta1  = (const float*)d_in[3];
    const float* W2     = (const float*)d_in[4];
    const float* gamma2 = (const float*)d_in[5];
    const float* beta2  = (const float*)d_in[6];
    const int*   nbr    = (const int*)d_in[7];
    const int*   mask   = (const int*)d_in[8];
    float* out = (float*)d_out;

    float *buf1, *buf2; unsigned short* wt; unsigned* pk; int* fidx;
    cudaGetSymbolAddress((void**)&buf1, g_buf1);
    cudaGetSymbolAddress((void**)&buf2, g_buf2);
    cudaGetSymbolAddress((void**)&wt,   g_wt);
    cudaGetSymbolAddress((void**)&pk,   g_pk);
    cudaGetSymbolAddress((void**)&fidx, g_fidx);

    cudaFuncSetAttribute(conv_mma, cudaFuncAttributeMaxDynamicSharedMemorySize, SM_TOT);

    const long long ne4 = (long long)NP*CH/4;
    const int gridb = (int)((ne4 + 255) / 256);
    const int gridp = (int)(((long long)NP*16 + 255) / 256);

    zero_stats<<<1,128>>>();
    prep_w<<<(2*KK*CH*CH + 255)/256, 256>>>(W1, W2);
    prep_fidx<<<NT2, 256>>>(nbr, mask, fidx);
    // pack feats -> pk; conv1: raw -> buf1, stats@0
    pack_input<<<gridp, 256>>>(feats, pk, 0, (const float*)0, (const float*)0);
    conv_mma<<<NT, TPB, SM_TOT>>>((const unsigned char*)pk, wt, fidx, buf1, 0);
    // h = relu(bn1(buf1)) packed -> pk; conv2: raw -> buf2, stats@64
    pack_input<<<gridp, 256>>>(buf1, pk, 1, gamma1, beta1);
    conv_mma<<<NT, TPB, SM_TOT>>>((const unsigned char*)pk, wt + KK*2048, fidx, buf2, 64);
    // out = relu(BN2(buf2) + feats)
    bnrelu_kernel<<<gridb, 256>>>((const float4*)buf2, 64, gamma2, beta2,
                                  (const float4*)feats, (float4*)out);
}

// round 9
// speedup vs baseline: 55.7157x; 1.1357x over previous
#include <cuda_runtime.h>
#include <cuda_fp16.h>

#define NP   400000
#define CH   32
#define KK   27
#define TPB  256
#define TILE 256
#define NT   ((NP + TILE - 1) / TILE)   // 1563
#define BT   256
#define NT2  ((NP + BT - 1) / BT)

// ---- device scratch (allocation-free rule) ----
__device__ float g_buf1[(size_t)NP*CH];
__device__ float g_buf2[(size_t)NP*CH];
__device__ float g_stats[128];                   // [0:64) conv1 sum/sumsq, [64:128) conv2
__device__ unsigned short g_wt[2][KK*1024];      // per-k 2KB fp16 W tiles, swizzled
__device__ unsigned g_pk[((size_t)NP+1)*16];     // packed fp16 rows 64B; row NP = zeros
__device__ int g_fidx[(size_t)KK*NP];            // k-major folded idx (mask applied; NP = inactive)

// ---- conv smem layout (bytes) ----
#define SM_W   0                        // 27*2048 = 55296
#define SM_ST  55296                    // 64 floats
#define SM_TOT (SM_ST + 256)            // 55552 -> 2 CTAs/SM (reg-capped)

// ============ helpers ============
__device__ __forceinline__ unsigned smem_u32(const void* p){
    unsigned a; asm("{ .reg .u64 t; cvta.to.shared.u64 t, %1; cvt.u32.u64 %0, t; }"
                    : "=r"(a) : "l"(p));
    return a;
}
__device__ __forceinline__ void ldmx4t(unsigned* r, unsigned addr){
    asm volatile("ldmatrix.sync.aligned.m8n8.x4.trans.shared.b16 {%0,%1,%2,%3}, [%4];"
        : "=r"(r[0]),"=r"(r[1]),"=r"(r[2]),"=r"(r[3]) : "r"(addr));
}
__device__ __forceinline__ void mma16816h(float* d, const unsigned* a, const unsigned* b){
    asm volatile("mma.sync.aligned.m16n8k16.row.col.f32.f16.f16.f32 "
        "{%0,%1,%2,%3}, {%4,%5,%6,%7}, {%8,%9}, {%0,%1,%2,%3};"
        : "+f"(d[0]),"+f"(d[1]),"+f"(d[2]),"+f"(d[3])
        : "r"(a[0]),"r"(a[1]),"r"(a[2]),"r"(a[3]), "r"(b[0]),"r"(b[1]));
}
__device__ __forceinline__ unsigned pack_f16(float x, float y){
    __half2 h = __floats2half2_rn(x, y);
    return *(unsigned*)&h;
}

// ============ W prep: fp32 -> swizzled fp16 tiles (B operand) ============
__global__ void prep_w(const float* __restrict__ W1, const float* __restrict__ W2){
    int idx = blockIdx.x*blockDim.x + threadIdx.x;
    if (idx >= 2*KK*CH*CH) return;
    int w   = idx / (KK*CH*CH);
    int rem = idx % (KK*CH*CH);
    int k = rem / (CH*CH);
    int i = (rem / CH) % CH;   // input channel  (GEMM K)  -> row
    int c = rem % CH;          // output channel (GEMM N)  -> col
    float v = (w ? W2 : W1)[(k*CH + i)*CH + c];
    unsigned off = i*64 + ((((unsigned)(c>>3)) ^ ((i>>1)&3)) << 4) + (c&7)*2;
    g_wt[w][k*1024 + (off>>1)] = __half_as_ushort(__float2half_rn(v));
}

__global__ void zero_stats(){
    if (threadIdx.x < 128) g_stats[threadIdx.x] = 0.f;
    if (threadIdx.x < 16)  g_pk[(size_t)NP*16 + threadIdx.x] = 0u;   // zero sentinel row
}

// ============ idx transpose: (n,k) row-major + mask -> k-major folded ============
__global__ void prep_fidx(const int* __restrict__ nbr, const int* __restrict__ mask,
                          int* __restrict__ fidx)
{
    __shared__ int tmp[KK][BT + 1];
    long long gbase = (long long)blockIdx.x * BT * KK;
    for (int j = threadIdx.x; j < BT*KK; j += blockDim.x){
        long long g = gbase + j;
        int v = NP;
        if (g < (long long)NP*KK && mask[g]) v = nbr[g];
        int nl = j / KK, k = j - nl*KK;
        tmp[k][nl] = v;
    }
    __syncthreads();
    int n = blockIdx.x*BT + threadIdx.x;
    if (n < NP){
        #pragma unroll 1
        for (int k = 0; k < KK; k++) fidx[(size_t)k*NP + n] = tmp[k][threadIdx.x];
    }
}

// ============ pack input: fp32 row -> 16 fp16-pair words, permuted word order ============
// word q (0..15) holds channel pair p = (q>>2) + 4*(q&3)
__global__ void pack_input(const float* __restrict__ src, unsigned* __restrict__ dst,
                           int bn, const float* __restrict__ gam, const float* __restrict__ bet)
{
    long long t = (long long)blockIdx.x*blockDim.x + threadIdx.x;
    if (t >= (long long)NP*16) return;
    int q   = (int)(t & 15);
    long long row = t >> 4;
    int p = (q >> 2) + 4*(q & 3);
    int c = 2*p;
    float2 v = *(const float2*)(src + row*CH + c);
    float x = v.x, y = v.y;
    if (bn){
        float m0 = g_stats[c]   * (1.f/NP), m1 = g_stats[c+1]   * (1.f/NP);
        float q0 = g_stats[32+c]* (1.f/NP), q1 = g_stats[32+c+1]* (1.f/NP);
        float s0 = rsqrtf(q0 - m0*m0 + 1e-5f) * gam[c];
        float s1 = rsqrtf(q1 - m1*m1 + 1e-5f) * gam[c+1];
        x = fmaxf(x*s0 + (bet[c]   - m0*s0), 0.f);
        y = fmaxf(y*s1 + (bet[c+1] - m1*s1), 0.f);
    }
    dst[row*16 + q] = pack_f16(x, y);
}

// ============ conv: fp16 single-term, depth-2 register pipeline ============
__global__ void __launch_bounds__(TPB,2) conv_mma(
    const unsigned char* __restrict__ pk, const unsigned short* __restrict__ wt,
    const int* __restrict__ fidx, float* __restrict__ out, int stats_off)
{
    extern __shared__ char smem[];
    const unsigned sb = smem_u32(smem);
    const int tid = threadIdx.x, w = tid >> 5, lane = tid & 31;
    const int gq = lane & 3, r_lo = lane >> 2;
    const int rbase = blockIdx.x*TILE + w*32 + r_lo;

    if (tid < 64) ((float*)(smem + SM_ST))[tid] = 0.f;
    // W tiles -> smem (55296B)
    {
        const uint4* s = (const uint4*)wt;
        uint4* d = (uint4*)(smem + SM_W);
        #pragma unroll 1
        for (int i = tid; i < (KK*2048)/16; i += TPB) d[i] = s[i];
    }
    __syncthreads();

    const int k0 = (w*27) >> 3;          // warp k-rotation (8 warps)
    int nrow[4];
    #pragma unroll
    for (int m = 0; m < 4; m++){ int n = rbase + m*8; nrow[m] = (n < NP) ? n : -1; }

    uint4 vh[2][4];
    int irC[4];

    // ---- prologue: issue j=0,1; preload idx for j=2 ----
    #pragma unroll
    for (int j = 0; j < 2; j++){
        int kk = k0 + j; if (kk >= KK) kk -= KK;
        #pragma unroll
        for (int m = 0; m < 4; m++){
            int ir = (nrow[m] >= 0) ? fidx[(size_t)kk*NP + nrow[m]] : NP;
            vh[j][m] = *(const uint4*)(pk + (size_t)ir*64 + gq*16);
        }
    }
    {
        int kk = k0 + 2; if (kk >= KK) kk -= KK;
        #pragma unroll
        for (int m = 0; m < 4; m++)
            irC[m] = (nrow[m] >= 0) ? fidx[(size_t)kk*NP + nrow[m]] : NP;
    }

    float acc[2][4][4];
    #pragma unroll
    for (int a = 0; a < 2; a++)
        #pragma unroll
        for (int b = 0; b < 4; b++)
            #pragma unroll
            for (int c = 0; c < 4; c++) acc[a][b][c] = 0.f;

    #pragma unroll 2
    for (int j = 0; j < KK; j++){
        const int buf = j & 1;
        int kk = k0 + j; if (kk >= KK) kk -= KK;

        // ---- snapshot fragments from arrived buffer ----
        unsigned ah[2][2][4];
        #pragma unroll
        for (int rb = 0; rb < 2; rb++){
            const unsigned* r0 = (const unsigned*)&vh[buf][2*rb];
            const unsigned* r1 = (const unsigned*)&vh[buf][2*rb+1];
            ah[rb][0][0]=r0[0]; ah[rb][0][1]=r1[0]; ah[rb][0][2]=r0[1]; ah[rb][0][3]=r1[1];
            ah[rb][1][0]=r0[2]; ah[rb][1][1]=r1[2]; ah[rb][1][2]=r0[3]; ah[rb][1][3]=r1[3];
        }

        // ---- issue j+2 into freed buffer ----
        if (j + 2 < KK){
            #pragma unroll
            for (int m = 0; m < 4; m++)
                vh[buf][m] = *(const uint4*)(pk + (size_t)irC[m]*64 + gq*16);
        }
        // ---- preload idx for j+3 ----
        if (j + 3 < KK){
            int k3 = k0 + j + 3; if (k3 >= KK) k3 -= KK;
            #pragma unroll
            for (int m = 0; m < 4; m++)
                irC[m] = (nrow[m] >= 0) ? fidx[(size_t)k3*NP + nrow[m]] : NP;
        }

        // ---- B per-nq + 16 mma ----
        const unsigned wk = sb + SM_W + kk*2048;
        #pragma unroll
        for (int nq = 0; nq < 4; nq++){
            unsigned bh[4];
            unsigned sw = ((((unsigned)nq) ^ ((lane>>1)&3)) << 4);
            ldmx4t(bh, wk + lane*64 + sw);
            #pragma unroll
            for (int rb = 0; rb < 2; rb++){
                mma16816h(acc[rb][nq], ah[rb][0], bh + 0);
                mma16816h(acc[rb][nq], ah[rb][1], bh + 2);
            }
        }
    }

    // ---- epilogue: store raw conv output + fused BN stats ----
    float sR[8], qR[8];
    #pragma unroll
    for (int i = 0; i < 8; i++){ sR[i] = 0.f; qR[i] = 0.f; }

    const int C0 = gq * 2;
    #pragma unroll
    for (int rb = 0; rb < 2; rb++){
        #pragma unroll
        for (int nq = 0; nq < 4; nq++){
            float a0 = acc[rb][nq][0], a1 = acc[rb][nq][1];
            float a2 = acc[rb][nq][2], a3 = acc[rb][nq][3];
            int m0 = rbase + rb*16, m1 = m0 + 8;
            int c  = nq*8 + C0;
            if (m0 < NP) *(float2*)(out + (size_t)m0*CH + c) = make_float2(a0, a1);
            if (m1 < NP) *(float2*)(out + (size_t)m1*CH + c) = make_float2(a2, a3);
            sR[nq*2+0] += a0 + a2;  qR[nq*2+0] += a0*a0 + a2*a2;
            sR[nq*2+1] += a1 + a3;  qR[nq*2+1] += a1*a1 + a3*a3;
        }
    }
    #pragma unroll
    for (int i = 0; i < 8; i++){
        #pragma unroll
        for (int off = 4; off < 32; off <<= 1){
            sR[i] += __shfl_xor_sync(0xffffffffu, sR[i], off);
            qR[i] += __shfl_xor_sync(0xffffffffu, qR[i], off);
        }
    }
    if (lane < 4){
        float* st = (float*)(smem + SM_ST);
        #pragma unroll
        for (int nq = 0; nq < 4; nq++){
            atomicAdd(&st[     nq*8 + lane*2    ], sR[nq*2+0]);
            atomicAdd(&st[     nq*8 + lane*2 + 1], sR[nq*2+1]);
            atomicAdd(&st[32 + nq*8 + lane*2    ], qR[nq*2+0]);
            atomicAdd(&st[32 + nq*8 + lane*2 + 1], qR[nq*2+1]);
        }
    }
    __syncthreads();
    if (tid < 64) atomicAdd(&g_stats[stats_off + tid], ((float*)(smem + SM_ST))[tid]);
}

// ---- final BN + residual + ReLU ----
__global__ void bnrelu_kernel(const float4* __restrict__ x, int stats_off,
    const float* __restrict__ gamma, const float* __restrict__ beta,
    const float4* __restrict__ res, float4* __restrict__ out)
{
    long long i = (long long)blockIdx.x*blockDim.x + threadIdx.x;
    if (i >= (long long)NP*CH/4) return;
    int c0 = (int)(i & 7) * 4;
    const float invN = 1.0f / NP;
    float4 v = x[i];
    float4 r4 = res[i];
    float4 o;
#define BN_ONE(comp, c) { \
        float mean = g_stats[stats_off + c0 + c] * invN; \
        float var  = g_stats[stats_off + 32 + c0 + c] * invN - mean*mean; \
        float sc   = rsqrtf(var + 1e-5f) * gamma[c0 + c]; \
        float val  = (v.comp - mean)*sc + beta[c0 + c] + r4.comp; \
        o.comp = fmaxf(val, 0.f); }
    BN_ONE(x, 0) BN_ONE(y, 1) BN_ONE(z, 2) BN_ONE(w, 3)
#undef BN_ONE
    out[i] = o;
}

extern "C" void kernel_launch(void* const* d_in, const int* in_sizes, int n_in,
                              void* d_out, int out_size)
{
    const float* feats  = (const float*)d_in[0];
    const float* W1     = (const float*)d_in[1];
    const float* gamma1 = (const float*)d_in[2];
    const float* beta1  = (const float*)d_in[3];
    const float* W2     = (const float*)d_in[4];
    const float* gamma2 = (const float*)d_in[5];
    const float* beta2  = (const float*)d_in[6];
    const int*   nbr    = (const int*)d_in[7];
    const int*   mask   = (const int*)d_in[8];
    float* out = (float*)d_out;

    float *buf1, *buf2; unsigned short* wt; unsigned* pk; int* fidx;
    cudaGetSymbolAddress((void**)&buf1, g_buf1);
    cudaGetSymbolAddress((void**)&buf2, g_buf2);
    cudaGetSymbolAddress((void**)&wt,   g_wt);
    cudaGetSymbolAddress((void**)&pk,   g_pk);
    cudaGetSymbolAddress((void**)&fidx, g_fidx);

    cudaFuncSetAttribute(conv_mma, cudaFuncAttributeMaxDynamicSharedMemorySize, SM_TOT);

    const long long ne4 = (long long)NP*CH/4;
    const int gridb = (int)((ne4 + 255) / 256);
    const int gridp = (int)(((long long)NP*16 + 255) / 256);

    zero_stats<<<1,128>>>();
    prep_w<<<(2*KK*CH*CH + 255)/256, 256>>>(W1, W2);
    prep_fidx<<<NT2, 256>>>(nbr, mask, fidx);
    // pack feats -> pk; conv1: raw -> buf1, stats@0
    pack_input<<<gridp, 256>>>(feats, pk, 0, (const float*)0, (const float*)0);
    conv_mma<<<NT, TPB, SM_TOT>>>((const unsigned char*)pk, wt, fidx, buf1, 0);
    // h = relu(bn1(buf1)) packed -> pk; conv2: raw -> buf2, stats@64
    pack_input<<<gridp, 256>>>(buf1, pk, 1, gamma1, beta1);
    conv_mma<<<NT, TPB, SM_TOT>>>((const unsigned char*)pk, wt + KK*1024, fidx, buf2, 64);
    // out = relu(BN2(buf2) + feats)
    bnrelu_kernel<<<gridb, 256>>>((const float4*)buf2, 64, gamma2, beta2,
                                  (const float4*)feats, (float4*)out);
}